// round 2
// baseline (speedup 1.0000x reference)
#include <cuda_runtime.h>
#include <cuda_bf16.h>
#include <cfloat>
#include <cstdint>

// Problem shape (fixed by the reference).
#define NB 32
#define TT 4000
#define DD 2048
#define RR 10

// Scratch for scores (device global — no allocation allowed).
__device__ float g_scores[NB * TT];

// ---------------------------------------------------------------------------
// Kernel 1: scores[n,t] = dot(x[n,t,:], w)   — one warp per row.
// D = 2048 floats = 512 float4; 32 lanes * 16 float4 each, coalesced.
// ---------------------------------------------------------------------------
__global__ __launch_bounds__(256) void score_kernel(
    const float* __restrict__ x,
    const float* __restrict__ w,
    float* __restrict__ scores)
{
    const int warp_global = (blockIdx.x * blockDim.x + threadIdx.x) >> 5;
    const int lane = threadIdx.x & 31;
    if (warp_global >= NB * TT) return;

    const float4* __restrict__ row = reinterpret_cast<const float4*>(
        x + (size_t)warp_global * DD);
    const float4* __restrict__ w4 = reinterpret_cast<const float4*>(w);

    float sum = 0.0f;
#pragma unroll
    for (int i = 0; i < 16; ++i) {
        const int idx = lane + i * 32;
        float4 a = row[idx];
        float4 b = w4[idx];
        sum = fmaf(a.x, b.x, sum);
        sum = fmaf(a.y, b.y, sum);
        sum = fmaf(a.z, b.z, sum);
        sum = fmaf(a.w, b.w, sum);
    }
    // warp reduction
#pragma unroll
    for (int off = 16; off > 0; off >>= 1)
        sum += __shfl_xor_sync(0xFFFFFFFFu, sum, off);

    if (lane == 0) scores[warp_global] = sum;
}

// ---------------------------------------------------------------------------
// Kernel 2: per-sequence Weldon pooling.
// out[n] = sigmoid( sum_r ( max_{t in bin r} s + min_{t in bin r} s ) )
// Bins: [r*L/R, ceil((r+1)*L/R)).  Never empty for L >= 1.
// One block per n (32 blocks, 256 threads).
// lengths arrive as int32 (harness converts int64 -> int32).
// ---------------------------------------------------------------------------
__global__ __launch_bounds__(256) void pool_kernel(
    const float* __restrict__ scores,
    const int* __restrict__ lengths,
    float* __restrict__ out)
{
    const int n = blockIdx.x;
    int L = lengths[n];
    // Defensive clamp: never index outside the scores row.
    if (L < 1) L = 1;
    if (L > TT) L = TT;
    const float* __restrict__ s = scores + (size_t)n * TT;

    __shared__ float smax[8];
    __shared__ float smin[8];
    __shared__ float acc;

    const int tid = threadIdx.x;
    const int lane = tid & 31;
    const int wid = tid >> 5;

    if (tid == 0) acc = 0.0f;
    __syncthreads();

    for (int r = 0; r < RR; ++r) {
        const int start = (r * L) / RR;
        const int end = ((r + 1) * L + (RR - 1)) / RR;

        float mx = -FLT_MAX;
        float mn = FLT_MAX;
        for (int t = start + tid; t < end; t += blockDim.x) {
            float v = s[t];
            mx = fmaxf(mx, v);
            mn = fminf(mn, v);
        }
        // warp reduce
#pragma unroll
        for (int off = 16; off > 0; off >>= 1) {
            mx = fmaxf(mx, __shfl_xor_sync(0xFFFFFFFFu, mx, off));
            mn = fminf(mn, __shfl_xor_sync(0xFFFFFFFFu, mn, off));
        }
        if (lane == 0) { smax[wid] = mx; smin[wid] = mn; }
        __syncthreads();
        if (tid == 0) {
            float bmx = smax[0], bmn = smin[0];
#pragma unroll
            for (int i = 1; i < 8; ++i) {
                bmx = fmaxf(bmx, smax[i]);
                bmn = fminf(bmn, smin[i]);
            }
            acc += bmx + bmn;
        }
        __syncthreads();
    }

    if (tid == 0) {
        float z = acc;
        out[n] = 1.0f / (1.0f + expf(-z));
    }
}

// ---------------------------------------------------------------------------
// kernel_launch
// Inputs (metadata order): x (float32, N*T*D), lengths (int32, N), w (float32, D)
// Output: float32, N
// ---------------------------------------------------------------------------
extern "C" void kernel_launch(void* const* d_in, const int* in_sizes, int n_in,
                              void* d_out, int out_size)
{
    const float* x = (const float*)d_in[0];
    const int* lengths = (const int*)d_in[1];
    const float* w = (const float*)d_in[2];
    float* out = (float*)d_out;

    float* scores;
    cudaGetSymbolAddress((void**)&scores, g_scores);

    // Kernel 1: NB*TT = 128000 warps, 8 warps/block -> 16000 blocks.
    const int total_warps = NB * TT;
    const int warps_per_block = 256 / 32;
    const int blocks = (total_warps + warps_per_block - 1) / warps_per_block;
    score_kernel<<<blocks, 256>>>(x, w, scores);

    // Kernel 2: one block per sequence.
    pool_kernel<<<NB, 256>>>(scores, lengths, out);
}

// round 3
// speedup vs baseline: 1.0731x; 1.0731x over previous
#include <cuda_runtime.h>
#include <cuda_bf16.h>
#include <cfloat>
#include <cstdint>

// Problem shape (fixed by the reference).
#define NB 32
#define TT 4000
#define DD 2048
#define RR 10

// Per-(n,r) pooling slots. Order-preserving float->uint encoding; 0 acts as -inf.
// Zero-initialized statics => first launch is clean; epilogue resets them so
// every graph replay starts clean (deterministic).
__device__ unsigned g_maxenc[NB * RR];   // max over bin of enc(s)
__device__ unsigned g_minenc[NB * RR];   // max over bin of enc(-s)  (= -min)

__device__ __forceinline__ unsigned enc_f(float v) {
    unsigned b = __float_as_uint(v);
    return (b & 0x80000000u) ? ~b : (b | 0x80000000u);
}
__device__ __forceinline__ float dec_f(unsigned u) {
    unsigned b = (u & 0x80000000u) ? (u & 0x7FFFFFFFu) : ~u;
    return __uint_as_float(b);
}

// ---------------------------------------------------------------------------
// Kernel 1: fused score + binned min/max pooling.
// One warp per (n,t) row: dot(x[n,t,:], w) -> warp reduce -> lane 0 atomically
// folds the score into every bin r whose [start_r, end_r) contains t.
// ---------------------------------------------------------------------------
__global__ __launch_bounds__(256) void score_pool_kernel(
    const float* __restrict__ x,
    const float* __restrict__ w,
    const int* __restrict__ lengths)
{
    const int warp_global = (blockIdx.x * blockDim.x + threadIdx.x) >> 5;
    const int lane = threadIdx.x & 31;
    if (warp_global >= NB * TT) return;

    const float4* __restrict__ row = reinterpret_cast<const float4*>(
        x + (size_t)warp_global * DD);
    const float4* __restrict__ w4 = reinterpret_cast<const float4*>(w);

    float sum = 0.0f;
#pragma unroll
    for (int i = 0; i < 16; ++i) {
        const int idx = lane + i * 32;
        float4 a = row[idx];
        float4 b = w4[idx];
        sum = fmaf(a.x, b.x, sum);
        sum = fmaf(a.y, b.y, sum);
        sum = fmaf(a.z, b.z, sum);
        sum = fmaf(a.w, b.w, sum);
    }
#pragma unroll
    for (int off = 16; off > 0; off >>= 1)
        sum += __shfl_xor_sync(0xFFFFFFFFu, sum, off);

    if (lane == 0) {
        const int n = warp_global / TT;
        const int t = warp_global - n * TT;
        int L = lengths[n];
        if (L < 1) L = 1;
        if (L > TT) L = TT;
        if (t < L) {
            const unsigned emax = enc_f(sum);
            const unsigned emin = enc_f(-sum);
#pragma unroll
            for (int r = 0; r < RR; ++r) {
                const int start = (r * L) / RR;
                const int end = ((r + 1) * L + (RR - 1)) / RR;
                if (t >= start && t < end) {
                    atomicMax(&g_maxenc[n * RR + r], emax);
                    atomicMax(&g_minenc[n * RR + r], emin);
                }
            }
        }
    }
}

// ---------------------------------------------------------------------------
// Kernel 2: epilogue. One block (320 threads).
// Threads 0..31 each reduce their sequence's 10 bins, apply sigmoid, write out.
// Then ALL threads reset the 320 slot pairs to 0 for the next replay.
// ---------------------------------------------------------------------------
__global__ __launch_bounds__(320) void epilogue_kernel(float* __restrict__ out)
{
    const int tid = threadIdx.x;

    if (tid < NB) {
        float acc = 0.0f;
#pragma unroll
        for (int r = 0; r < RR; ++r) {
            const float mx = dec_f(g_maxenc[tid * RR + r]);
            const float mn = -dec_f(g_minenc[tid * RR + r]);
            acc += mx + mn;
        }
        out[tid] = 1.0f / (1.0f + expf(-acc));
    }
    __syncthreads();
    // Reset slots so the next graph replay starts from a clean state.
    g_maxenc[tid] = 0u;
    g_minenc[tid] = 0u;
}

// ---------------------------------------------------------------------------
// kernel_launch
// Inputs (metadata order): x (float32, N*T*D), lengths (int32, N), w (float32, D)
// Output: float32, N
// ---------------------------------------------------------------------------
extern "C" void kernel_launch(void* const* d_in, const int* in_sizes, int n_in,
                              void* d_out, int out_size)
{
    const float* x = (const float*)d_in[0];
    const int* lengths = (const int*)d_in[1];
    const float* w = (const float*)d_in[2];
    float* out = (float*)d_out;

    const int total_warps = NB * TT;            // 128000
    const int warps_per_block = 256 / 32;       // 8
    const int blocks = (total_warps + warps_per_block - 1) / warps_per_block;
    score_pool_kernel<<<blocks, 256>>>(x, w, lengths);

    epilogue_kernel<<<1, NB * RR>>>(out);
}

// round 6
// speedup vs baseline: 1.6028x; 1.4936x over previous
#include <cuda_runtime.h>
#include <cuda_bf16.h>
#include <cfloat>
#include <cstdint>

// Problem shape (fixed by the reference).
#define NB 32
#define TT 4000
#define DD 2048
#define RR 10

// Per-(n,r) pooling slots. Order-preserving float->uint encoding; 0 acts as -inf.
// Zero-initialized statics => first launch clean; last block resets via
// atomicExch so every graph replay starts clean (deterministic).
__device__ unsigned g_maxenc[NB * RR];   // max over bin of enc(s)
__device__ unsigned g_minenc[NB * RR];   // max over bin of enc(-s)  (= -min)
__device__ unsigned g_done;              // ticket counter for last-block epilogue

__device__ __forceinline__ unsigned enc_f(float v) {
    unsigned b = __float_as_uint(v);
    return (b & 0x80000000u) ? ~b : (b | 0x80000000u);
}
__device__ __forceinline__ float dec_f(unsigned u) {
    unsigned b = (u & 0x80000000u) ? (u & 0x7FFFFFFFu) : ~u;
    return __uint_as_float(b);
}

// ---------------------------------------------------------------------------
// Fused kernel: score GEMV + binned min/max pooling + last-block epilogue.
// One warp per (n,t) row. Rows with t >= L are masked out by the reference,
// so we skip their dot product entirely -> their x rows are never loaded
// (halves expected DRAM traffic).
// ---------------------------------------------------------------------------
__global__ __launch_bounds__(256) void weldon_kernel(
    const float* __restrict__ x,
    const float* __restrict__ w,
    const int* __restrict__ lengths,
    float* __restrict__ out)
{
    const int warp_global = (blockIdx.x * blockDim.x + threadIdx.x) >> 5;
    const int lane = threadIdx.x & 31;

    if (warp_global < NB * TT) {
        const int n = warp_global / TT;
        const int t = warp_global - n * TT;
        int L = lengths[n];
        if (L < 1) L = 1;
        if (L > TT) L = TT;

        if (t < L) {
            const float4* __restrict__ row = reinterpret_cast<const float4*>(
                x + (size_t)warp_global * DD);
            const float4* __restrict__ w4 = reinterpret_cast<const float4*>(w);

            float sum = 0.0f;
#pragma unroll
            for (int i = 0; i < 16; ++i) {
                const int idx = lane + i * 32;
                float4 a = row[idx];
                float4 b = w4[idx];
                sum = fmaf(a.x, b.x, sum);
                sum = fmaf(a.y, b.y, sum);
                sum = fmaf(a.z, b.z, sum);
                sum = fmaf(a.w, b.w, sum);
            }
#pragma unroll
            for (int off = 16; off > 0; off >>= 1)
                sum += __shfl_xor_sync(0xFFFFFFFFu, sum, off);

            if (lane == 0) {
                const unsigned emax = enc_f(sum);
                const unsigned emin = enc_f(-sum);
#pragma unroll
                for (int r = 0; r < RR; ++r) {
                    const int start = (r * L) / RR;
                    const int end = ((r + 1) * L + (RR - 1)) / RR;
                    if (t >= start && t < end) {
                        atomicMax(&g_maxenc[n * RR + r], emax);
                        atomicMax(&g_minenc[n * RR + r], emin);
                    }
                }
                // Make this warp's atomics device-visible before the block's
                // ticket increment (cumulative fence; canonical pattern).
                __threadfence();
            }
        }
    }

    __syncthreads();

    // Last-block epilogue.
    __shared__ bool s_last;
    if (threadIdx.x == 0) {
        unsigned ticket = atomicAdd(&g_done, 1u);
        s_last = (ticket == gridDim.x - 1);
    }
    __syncthreads();

    if (s_last) {
        const int tid = threadIdx.x;
        if (tid < NB) {
            float acc = 0.0f;
#pragma unroll
            for (int r = 0; r < RR; ++r) {
                // atomicExch: L2-coherent read of the final value AND reset
                // to 0 (= -inf) for the next graph replay.
                const float mx = dec_f(atomicExch(&g_maxenc[tid * RR + r], 0u));
                const float mn = -dec_f(atomicExch(&g_minenc[tid * RR + r], 0u));
                acc += mx + mn;
            }
            out[tid] = 1.0f / (1.0f + expf(-acc));
        }
        if (tid == 0) {
            g_done = 0u;   // reset ticket for next replay
        }
    }
}

// ---------------------------------------------------------------------------
// kernel_launch
// Inputs (metadata order): x (float32, N*T*D), lengths (int32, N), w (float32, D)
// Output: float32, N
// ---------------------------------------------------------------------------
extern "C" void kernel_launch(void* const* d_in, const int* in_sizes, int n_in,
                              void* d_out, int out_size)
{
    const float* x = (const float*)d_in[0];
    const int* lengths = (const int*)d_in[1];
    const float* w = (const float*)d_in[2];
    float* out = (float*)d_out;

    const int total_warps = NB * TT;            // 128000
    const int warps_per_block = 256 / 32;       // 8
    const int blocks = (total_warps + warps_per_block - 1) / warps_per_block;
    weldon_kernel<<<blocks, 256>>>(x, w, lengths, out);
}